// round 15
// baseline (speedup 1.0000x reference)
#include <cuda_runtime.h>
#include <cfloat>
#include <climits>
#include <cstdint>

// Problem geometry:
//   data_in : [1, 512] f32      (d_in[0])
//   ukb_mat : [200000, 512] f32 (d_in[1])
//   pseudo  : [200000] f32      (d_in[2])
//   K       : 3
// out: [1] f32 = mean(pseudo[indices of 3 smallest L1 distances])
//
// Self-paced per-warp bulk-async rings:
//   - No producer warp, no empty barriers. Each of 8 warps owns a private
//     3-slot x 4KB ring (one row PAIR per slot) and refills its own slot right
//     after reading it (syncwarp -> lane0 expect_tx + cp.async.bulk). Slot
//     refill latency ~0; zero cross-warp coupling in the hot loop.
//   - 2 CTAs/SM x 96KB = 192KB in flight per SM.
//   - Packed dual warp reduction (6 shuffles / 2 rows); packed-u64 (dist,idx)
//     top-3 keys; last-block-done global merge.

constexpr int D        = 512;
constexpr int D4       = D / 4;
constexpr int KSEL     = 3;
constexpr int BLOCKS1  = 296;                  // 2 CTAs/SM * 148 SMs
constexpr int NWARPS   = 8;
constexpr int THREADS1 = NWARPS * 32;          // 256
constexpr int STAGES   = 3;                    // slots per warp
constexpr int PAIR_B   = 2 * D * 4;            // 4096 bytes per row pair
constexpr int PAIR_F4  = 2 * D4;               // 256 float4
constexpr int SMEM_DYN = NWARPS * STAGES * PAIR_B;   // 98304 B
constexpr int NCAND    = BLOCKS1 * KSEL;       // 888

__device__ unsigned long long g_cand[NCAND];
__device__ unsigned int       g_counter;       // zero-init; self-reset each run

__device__ __forceinline__ unsigned long long mkkey(float d, unsigned idx) {
    return ((unsigned long long)__float_as_uint(d) << 32) | idx;
}
constexpr unsigned long long KEY_MAX = 0xFFFFFFFFFFFFFFFFull;

__device__ __forceinline__ void insert3(unsigned long long v, unsigned long long k[3]) {
    if (v < k[2]) {
        k[2] = v;
        if (k[2] < k[1]) { unsigned long long t = k[1]; k[1] = k[2]; k[2] = t;
            if (k[1] < k[0]) { t = k[0]; k[0] = k[1]; k[1] = t; }
        }
    }
}

__device__ __forceinline__ void warp_merge3(unsigned long long k[3]) {
    #pragma unroll
    for (int o = 16; o > 0; o >>= 1) {
        unsigned long long b0 = __shfl_xor_sync(0xFFFFFFFFu, k[0], o);
        unsigned long long b1 = __shfl_xor_sync(0xFFFFFFFFu, k[1], o);
        unsigned long long b2 = __shfl_xor_sync(0xFFFFFFFFu, k[2], o);
        insert3(b0, k); insert3(b1, k); insert3(b2, k);
    }
}

__device__ __forceinline__ float l1_4(float4 a, float4 q) {
    return fabsf(a.x - q.x) + fabsf(a.y - q.y) + fabsf(a.z - q.z) + fabsf(a.w - q.w);
}

// ---- mbarrier / bulk-async PTX helpers -------------------------------------
__device__ __forceinline__ uint32_t smem_u32(const void* p) {
    return (uint32_t)__cvta_generic_to_shared(p);
}
__device__ __forceinline__ void mbar_init(uint32_t mbar, uint32_t count) {
    asm volatile("mbarrier.init.shared.b64 [%0], %1;" :: "r"(mbar), "r"(count) : "memory");
}
__device__ __forceinline__ void mbar_expect_tx(uint32_t mbar, uint32_t bytes) {
    asm volatile("mbarrier.arrive.expect_tx.shared.b64 _, [%0], %1;"
                 :: "r"(mbar), "r"(bytes) : "memory");
}
__device__ __forceinline__ void mbar_wait(uint32_t mbar, uint32_t parity) {
    uint32_t done;
    asm volatile(
        "{\n\t.reg .pred p;\n\t"
        "mbarrier.try_wait.parity.acquire.cta.shared::cta.b64 p, [%1], %2;\n\t"
        "selp.b32 %0, 1, 0, p;\n\t}"
        : "=r"(done) : "r"(mbar), "r"(parity) : "memory");
    if (!done) {
        asm volatile(
            "{\n\t.reg .pred P1;\n\t"
            "WAIT_LOOP_%=:\n\t"
            "mbarrier.try_wait.parity.acquire.cta.shared::cta.b64 P1, [%0], %1, 0x989680;\n\t"
            "@P1 bra.uni WAIT_DONE_%=;\n\t"
            "bra.uni WAIT_LOOP_%=;\n\t"
            "WAIT_DONE_%=:\n\t}"
            :: "r"(mbar), "r"(parity) : "memory");
    }
}
__device__ __forceinline__ void bulk_ldg(uint32_t dst_smem, const void* src, uint32_t bytes,
                                         uint32_t mbar) {
    asm volatile(
        "cp.async.bulk.shared::cluster.global.mbarrier::complete_tx::bytes "
        "[%0], [%1], %2, [%3];"
        :: "r"(dst_smem), "l"(src), "r"(bytes), "r"(mbar) : "memory");
}
// ----------------------------------------------------------------------------

__global__ __launch_bounds__(THREADS1, 2)
void knn_fused_kernel(const float* __restrict__ query,
                      const float* __restrict__ mat,
                      const float* __restrict__ pseudo,
                      float* __restrict__ out,
                      int N) {
    extern __shared__ float4 ring[];               // NWARPS*STAGES*PAIR_B bytes
    __shared__ unsigned long long full_bar[NWARPS][STAGES];
    __shared__ unsigned long long sk[NWARPS * KSEL];
    __shared__ int s_last;

    const int tid  = threadIdx.x;
    const int lane = tid & 31;
    const int warp = tid >> 5;

    if (tid == 0) {
        for (int w = 0; w < NWARPS; w++)
            for (int s = 0; s < STAGES; s++)
                mbar_init(smem_u32(&full_bar[w][s]), 1);   // complete_tx driven
        asm volatile("fence.proxy.async.shared::cta;" ::: "memory");
    }
    __syncthreads();

    const int bid    = blockIdx.x;
    const int gwarp  = bid * NWARPS + warp;
    const int nwarp  = BLOCKS1 * NWARPS;
    const int npairs = N >> 1;

    const float4* q4 = reinterpret_cast<const float4*>(query);
    const float4 q0 = __ldg(q4 + lane +  0);
    const float4 q1 = __ldg(q4 + lane + 32);
    const float4 q2 = __ldg(q4 + lane + 64);
    const float4 q3 = __ldg(q4 + lane + 96);

    unsigned long long k[3] = {KEY_MAX, KEY_MAX, KEY_MAX};

    float4* myring = ring + warp * (STAGES * PAIR_F4);
    const char* matc = reinterpret_cast<const char*>(mat);

    // Prologue: lane 0 fills this warp's private ring.
    if (lane == 0) {
        #pragma unroll
        for (int s = 0; s < STAGES; s++) {
            int p = gwarp + s * nwarp;
            if (p < npairs) {
                uint32_t mb = smem_u32(&full_bar[warp][s]);
                mbar_expect_tx(mb, PAIR_B);
                bulk_ldg(smem_u32(myring) + s * PAIR_B,
                         matc + (size_t)p * PAIR_B, PAIR_B, mb);
            }
        }
    }
    __syncwarp();

    int slot = 0, phase = 0;
    int fill = gwarp + STAGES * nwarp;
    for (int p = gwarp; p < npairs; p += nwarp) {
        mbar_wait(smem_u32(&full_bar[warp][slot]), (uint32_t)phase);
        const float4* st = myring + slot * PAIR_F4;
        float4 a0 = st[lane +  0];
        float4 a1 = st[lane + 32];
        float4 a2 = st[lane + 64];
        float4 a3 = st[lane + 96];
        float4 b0 = st[D4 + lane +  0];
        float4 b1 = st[D4 + lane + 32];
        float4 b2 = st[D4 + lane + 64];
        float4 b3 = st[D4 + lane + 96];
        // All lanes' reads complete before the slot is overwritten.
        __syncwarp();
        if (lane == 0 && fill < npairs) {
            uint32_t mb = smem_u32(&full_bar[warp][slot]);
            mbar_expect_tx(mb, PAIR_B);
            bulk_ldg(smem_u32(myring) + slot * PAIR_B,
                     matc + (size_t)fill * PAIR_B, PAIR_B, mb);
        }
        fill += nwarp;

        float sa = l1_4(a0, q0) + l1_4(a1, q1) + l1_4(a2, q2) + l1_4(a3, q3);
        float sb = l1_4(b0, q0) + l1_4(b1, q1) + l1_4(b2, q2) + l1_4(b3, q3);
        // Packed dual reduction: row a -> lanes 0-15, row b -> lanes 16-31.
        float va = sa + __shfl_xor_sync(0xFFFFFFFFu, sa, 16);
        float vb = sb + __shfl_xor_sync(0xFFFFFFFFu, sb, 16);
        float v  = (lane < 16) ? va : vb;
        #pragma unroll
        for (int o = 8; o > 0; o >>= 1)
            v += __shfl_xor_sync(0xFFFFFFFFu, v, o);
        int row = 2 * p;
        if (lane == 0)       insert3(mkkey(v, (unsigned)row),       k);
        else if (lane == 16) insert3(mkkey(v, (unsigned)(row + 1)), k);

        if (++slot == STAGES) { slot = 0; phase ^= 1; }
    }

    // Odd-N tail: one leftover row, block 0 warp 0, direct loads.
    if ((N & 1) && gwarp == 0) {
        const float4* ra = reinterpret_cast<const float4*>(mat) + (size_t)(N - 1) * D4;
        float s = l1_4(__ldg(ra + lane +  0), q0) + l1_4(__ldg(ra + lane + 32), q1)
                + l1_4(__ldg(ra + lane + 64), q2) + l1_4(__ldg(ra + lane + 96), q3);
        #pragma unroll
        for (int o = 16; o > 0; o >>= 1)
            s += __shfl_xor_sync(0xFFFFFFFFu, s, o);
        if (lane == 0) insert3(mkkey(s, (unsigned)(N - 1)), k);
    }

    // ---- block merge ----
    warp_merge3(k);
    if (lane == 0) {
        #pragma unroll
        for (int j = 0; j < KSEL; j++) sk[warp * KSEL + j] = k[j];
    }
    __syncthreads();
    if (tid == 0) {
        unsigned long long bk[3] = {KEY_MAX, KEY_MAX, KEY_MAX};
        #pragma unroll
        for (int j = 0; j < NWARPS * KSEL; j++) insert3(sk[j], bk);
        #pragma unroll
        for (int j = 0; j < KSEL; j++) g_cand[bid * KSEL + j] = bk[j];
    }

    // ---- last-block-done global merge ----
    if (tid == 0) {
        __threadfence();
        unsigned v = atomicAdd(&g_counter, 1u);
        s_last = (v == BLOCKS1 - 1) ? 1 : 0;
    }
    __syncthreads();
    if (!s_last) return;

    unsigned long long m[3] = {KEY_MAX, KEY_MAX, KEY_MAX};
    volatile unsigned long long* cand = g_cand;
    for (int j = tid; j < NCAND; j += THREADS1)
        insert3(cand[j], m);
    warp_merge3(m);

    __shared__ unsigned long long fk[NWARPS * KSEL];
    if (lane == 0) {
        #pragma unroll
        for (int j = 0; j < KSEL; j++) fk[warp * KSEL + j] = m[j];
    }
    __syncthreads();
    if (tid == 0) {
        unsigned long long bk[3] = {KEY_MAX, KEY_MAX, KEY_MAX};
        #pragma unroll
        for (int j = 0; j < NWARPS * KSEL; j++) insert3(fk[j], bk);
        unsigned i0 = (unsigned)(bk[0] & 0xFFFFFFFFull);
        unsigned i1 = (unsigned)(bk[1] & 0xFFFFFFFFull);
        unsigned i2 = (unsigned)(bk[2] & 0xFFFFFFFFull);
        out[0] = (pseudo[i0] + pseudo[i1] + pseudo[i2]) * (1.0f / 3.0f);
        g_counter = 0;   // reset for next graph replay
    }
}

extern "C" void kernel_launch(void* const* d_in, const int* in_sizes, int n_in,
                              void* d_out, int out_size) {
    const float* query  = (const float*)d_in[0];
    const float* mat    = (const float*)d_in[1];
    const float* pseudo = (const float*)d_in[2];
    float* out = (float*)d_out;
    const int N = in_sizes[2];

    static bool attr_set = false;
    if (!attr_set) {
        cudaFuncSetAttribute(knn_fused_kernel,
                             cudaFuncAttributeMaxDynamicSharedMemorySize, SMEM_DYN);
        attr_set = true;
    }
    knn_fused_kernel<<<BLOCKS1, THREADS1, SMEM_DYN>>>(query, mat, pseudo, out, N);
}

// round 16
// speedup vs baseline: 1.0360x; 1.0360x over previous
#include <cuda_runtime.h>
#include <cfloat>
#include <climits>
#include <cstdint>

// Problem geometry:
//   data_in : [1, 512] f32      (d_in[0])
//   ukb_mat : [200000, 512] f32 (d_in[1])
//   pseudo  : [200000] f32      (d_in[2])
//   K       : 3
// out: [1] f32 = mean(pseudo[indices of 3 smallest L1 distances])
//
// Bulk-async producer/consumer pipeline (best-known R14 shape) with
// L2 evict-first cache-hint on the bulk copies (single-use stream):
//   - 8 consecutive rows = one contiguous 16KB tile; producer warp issues ONE
//     cp.async.bulk per tile into a 4-stage smem ring (64KB/CTA, 3 CTAs/SM,
//     192KB in flight and 27 warps per SM).
//   - 8 consumer warps: warp w reduces row w of each tile (4x conflict-free
//     LDS.128 + 5-shuffle butterfly), query held in registers.
//   - packed-u64 (dist,idx) top-3 keys; last-block-done global merge.

constexpr int D         = 512;
constexpr int D4        = D / 4;
constexpr int KSEL      = 3;
constexpr int BLOCKS1   = 444;                 // 3 CTAs/SM * 148 SMs
constexpr int CONS_W    = 8;                   // consumer warps
constexpr int THREADS1  = (CONS_W + 1) * 32;   // 288
constexpr int NWARPS    = CONS_W + 1;
constexpr int ROWS_TILE = 8;
constexpr int TILE_B    = ROWS_TILE * D * 4;   // 16384 bytes
constexpr int STAGES    = 4;
constexpr int SMEM_DYN  = STAGES * TILE_B;     // 65536 B ring
constexpr int NCAND     = BLOCKS1 * KSEL;      // 1332

__device__ unsigned long long g_cand[NCAND];
__device__ unsigned int       g_counter;       // zero-init; self-reset each run

__device__ __forceinline__ unsigned long long mkkey(float d, unsigned idx) {
    return ((unsigned long long)__float_as_uint(d) << 32) | idx;
}
constexpr unsigned long long KEY_MAX = 0xFFFFFFFFFFFFFFFFull;

__device__ __forceinline__ void insert3(unsigned long long v, unsigned long long k[3]) {
    if (v < k[2]) {
        k[2] = v;
        if (k[2] < k[1]) { unsigned long long t = k[1]; k[1] = k[2]; k[2] = t;
            if (k[1] < k[0]) { t = k[0]; k[0] = k[1]; k[1] = t; }
        }
    }
}

__device__ __forceinline__ void warp_merge3(unsigned long long k[3]) {
    #pragma unroll
    for (int o = 16; o > 0; o >>= 1) {
        unsigned long long b0 = __shfl_xor_sync(0xFFFFFFFFu, k[0], o);
        unsigned long long b1 = __shfl_xor_sync(0xFFFFFFFFu, k[1], o);
        unsigned long long b2 = __shfl_xor_sync(0xFFFFFFFFu, k[2], o);
        insert3(b0, k); insert3(b1, k); insert3(b2, k);
    }
}

__device__ __forceinline__ float l1_4(float4 a, float4 q) {
    return fabsf(a.x - q.x) + fabsf(a.y - q.y) + fabsf(a.z - q.z) + fabsf(a.w - q.w);
}

// ---- mbarrier / bulk-async PTX helpers -------------------------------------
__device__ __forceinline__ uint32_t smem_u32(const void* p) {
    return (uint32_t)__cvta_generic_to_shared(p);
}
__device__ __forceinline__ void mbar_init(uint32_t mbar, uint32_t count) {
    asm volatile("mbarrier.init.shared.b64 [%0], %1;" :: "r"(mbar), "r"(count) : "memory");
}
__device__ __forceinline__ void mbar_expect_tx(uint32_t mbar, uint32_t bytes) {
    asm volatile("mbarrier.arrive.expect_tx.shared.b64 _, [%0], %1;"
                 :: "r"(mbar), "r"(bytes) : "memory");
}
__device__ __forceinline__ void mbar_arrive(uint32_t mbar) {
    asm volatile("mbarrier.arrive.shared.b64 _, [%0];" :: "r"(mbar) : "memory");
}
// Acquire wait: consumers (generic LDS after wait needs ordering).
__device__ __forceinline__ void mbar_wait(uint32_t mbar, uint32_t parity) {
    uint32_t done;
    asm volatile(
        "{\n\t.reg .pred p;\n\t"
        "mbarrier.try_wait.parity.acquire.cta.shared::cta.b64 p, [%1], %2;\n\t"
        "selp.b32 %0, 1, 0, p;\n\t}"
        : "=r"(done) : "r"(mbar), "r"(parity) : "memory");
    if (!done) {
        asm volatile(
            "{\n\t.reg .pred P1;\n\t"
            "WAIT_LOOP_%=:\n\t"
            "mbarrier.try_wait.parity.acquire.cta.shared::cta.b64 P1, [%0], %1, 0x989680;\n\t"
            "@P1 bra.uni WAIT_DONE_%=;\n\t"
            "bra.uni WAIT_LOOP_%=;\n\t"
            "WAIT_DONE_%=:\n\t}"
            :: "r"(mbar), "r"(parity) : "memory");
    }
}
// Relaxed wait: producer only (post-wait accesses are async-proxy bulk copies).
__device__ __forceinline__ void mbar_wait_relaxed(uint32_t mbar, uint32_t parity) {
    uint32_t done;
    asm volatile(
        "{\n\t.reg .pred p;\n\t"
        "mbarrier.try_wait.parity.relaxed.cta.shared::cta.b64 p, [%1], %2;\n\t"
        "selp.b32 %0, 1, 0, p;\n\t}"
        : "=r"(done) : "r"(mbar), "r"(parity) : "memory");
    if (!done) {
        asm volatile(
            "{\n\t.reg .pred P1;\n\t"
            "WAIT_LOOP_%=:\n\t"
            "mbarrier.try_wait.parity.relaxed.cta.shared::cta.b64 P1, [%0], %1, 0x989680;\n\t"
            "@P1 bra.uni WAIT_DONE_%=;\n\t"
            "bra.uni WAIT_LOOP_%=;\n\t"
            "WAIT_DONE_%=:\n\t}"
            :: "r"(mbar), "r"(parity) : "memory");
    }
}
// Bulk copy with L2 evict-first hint: single-use stream, don't let dead
// tiles occupy L2 ways.
__device__ __forceinline__ void bulk_ldg_ef(uint32_t dst_smem, const void* src,
                                            uint32_t bytes, uint32_t mbar) {
    asm volatile(
        "{\n\t.reg .b64 pol;\n\t"
        "createpolicy.fractional.L2::evict_first.b64 pol, 1.0;\n\t"
        "cp.async.bulk.shared::cluster.global.mbarrier::complete_tx::bytes.L2::cache_hint "
        "[%0], [%1], %2, [%3], pol;\n\t}"
        :: "r"(dst_smem), "l"(src), "r"(bytes), "r"(mbar) : "memory");
}
// ----------------------------------------------------------------------------

__global__ __launch_bounds__(THREADS1, 3)
void knn_fused_kernel(const float* __restrict__ query,
                      const float* __restrict__ mat,
                      const float* __restrict__ pseudo,
                      float* __restrict__ out,
                      int N) {
    extern __shared__ float4 stages[];                  // STAGES * TILE_B bytes
    __shared__ unsigned long long full_bar[STAGES];
    __shared__ unsigned long long empty_bar[STAGES];
    __shared__ unsigned long long sk[NWARPS * KSEL];
    __shared__ int s_last;

    const int tid  = threadIdx.x;
    const int lane = tid & 31;
    const int warp = tid >> 5;

    if (tid == 0) {
        #pragma unroll
        for (int s = 0; s < STAGES; s++) {
            mbar_init(smem_u32(&full_bar[s]),  1);       // complete_tx driven
            mbar_init(smem_u32(&empty_bar[s]), CONS_W);  // one arrive per consumer warp
        }
        asm volatile("fence.proxy.async.shared::cta;" ::: "memory");
    }
    __syncthreads();

    const int ntiles = N >> 3;           // 8 rows per tile
    const int nleft  = N & 7;
    const int bid    = blockIdx.x;

    unsigned long long k[3] = {KEY_MAX, KEY_MAX, KEY_MAX};

    if (warp == CONS_W) {
        // ---- producer warp: elected lane streams tiles into the ring ----
        if (lane == 0) {
            int slot = 0, phase = 1;     // fresh empty barrier: parity-1 wait passes
            for (int t = bid; t < ntiles; t += BLOCKS1) {
                mbar_wait_relaxed(smem_u32(&empty_bar[slot]), (uint32_t)phase);
                uint32_t mb = smem_u32(&full_bar[slot]);
                mbar_expect_tx(mb, TILE_B);
                const char* src = reinterpret_cast<const char*>(mat) + (size_t)t * TILE_B;
                bulk_ldg_ef(smem_u32(stages) + slot * TILE_B, src, TILE_B, mb);
                if (++slot == STAGES) { slot = 0; phase ^= 1; }
            }
        }
    } else {
        // ---- consumer warps: warp w reduces row w of every tile ----
        const float4* q4 = reinterpret_cast<const float4*>(query);
        const float4 q0 = __ldg(q4 + lane +  0);
        const float4 q1 = __ldg(q4 + lane + 32);
        const float4 q2 = __ldg(q4 + lane + 64);
        const float4 q3 = __ldg(q4 + lane + 96);

        int slot = 0, phase = 0;
        for (int t = bid; t < ntiles; t += BLOCKS1) {
            mbar_wait(smem_u32(&full_bar[slot]), (uint32_t)phase);
            const float4* r = stages + slot * (TILE_B / 16) + warp * D4;
            float4 a0 = r[lane +  0];
            float4 a1 = r[lane + 32];
            float4 a2 = r[lane + 64];
            float4 a3 = r[lane + 96];
            float s = l1_4(a0, q0) + l1_4(a1, q1) + l1_4(a2, q2) + l1_4(a3, q3);
            // Slot consumed by this warp -> release before the shuffle tail so
            // the producer refills during it.
            if (lane == 0) mbar_arrive(smem_u32(&empty_bar[slot]));
            #pragma unroll
            for (int o = 16; o > 0; o >>= 1)
                s += __shfl_xor_sync(0xFFFFFFFFu, s, o);
            if (lane == 0) insert3(mkkey(s, (unsigned)(t * ROWS_TILE + warp)), k);
            if (++slot == STAGES) { slot = 0; phase ^= 1; }
        }

        // Leftover rows (N % 8): block 0, warp w takes row ntiles*8 + w.
        if (nleft && bid == 0 && warp < nleft) {
            const float4* ra = reinterpret_cast<const float4*>(mat) +
                               (size_t)(ntiles * ROWS_TILE + warp) * D4;
            float s = l1_4(__ldg(ra + lane +  0), q0) + l1_4(__ldg(ra + lane + 32), q1)
                    + l1_4(__ldg(ra + lane + 64), q2) + l1_4(__ldg(ra + lane + 96), q3);
            #pragma unroll
            for (int o = 16; o > 0; o >>= 1)
                s += __shfl_xor_sync(0xFFFFFFFFu, s, o);
            if (lane == 0) insert3(mkkey(s, (unsigned)(ntiles * ROWS_TILE + warp)), k);
        }
    }

    // ---- block merge (lane 0 of each warp holds its top-3; producer = MAX) ----
    if (lane == 0) {
        #pragma unroll
        for (int j = 0; j < KSEL; j++) sk[warp * KSEL + j] = k[j];
    }
    __syncthreads();
    if (tid == 0) {
        unsigned long long bk[3] = {KEY_MAX, KEY_MAX, KEY_MAX};
        #pragma unroll
        for (int j = 0; j < NWARPS * KSEL; j++) insert3(sk[j], bk);
        #pragma unroll
        for (int j = 0; j < KSEL; j++) g_cand[bid * KSEL + j] = bk[j];
    }

    // ---- last-block-done global merge ----
    if (tid == 0) {
        __threadfence();
        unsigned v = atomicAdd(&g_counter, 1u);
        s_last = (v == BLOCKS1 - 1) ? 1 : 0;
    }
    __syncthreads();
    if (!s_last) return;

    unsigned long long m[3] = {KEY_MAX, KEY_MAX, KEY_MAX};
    volatile unsigned long long* cand = g_cand;
    for (int j = tid; j < NCAND; j += THREADS1)
        insert3(cand[j], m);
    warp_merge3(m);

    __shared__ unsigned long long fk[NWARPS * KSEL];
    if (lane == 0) {
        #pragma unroll
        for (int j = 0; j < KSEL; j++) fk[warp * KSEL + j] = m[j];
    }
    __syncthreads();
    if (tid == 0) {
        unsigned long long bk[3] = {KEY_MAX, KEY_MAX, KEY_MAX};
        #pragma unroll
        for (int j = 0; j < NWARPS * KSEL; j++) insert3(fk[j], bk);
        unsigned i0 = (unsigned)(bk[0] & 0xFFFFFFFFull);
        unsigned i1 = (unsigned)(bk[1] & 0xFFFFFFFFull);
        unsigned i2 = (unsigned)(bk[2] & 0xFFFFFFFFull);
        out[0] = (pseudo[i0] + pseudo[i1] + pseudo[i2]) * (1.0f / 3.0f);
        g_counter = 0;   // reset for next graph replay
    }
}

extern "C" void kernel_launch(void* const* d_in, const int* in_sizes, int n_in,
                              void* d_out, int out_size) {
    const float* query  = (const float*)d_in[0];
    const float* mat    = (const float*)d_in[1];
    const float* pseudo = (const float*)d_in[2];
    float* out = (float*)d_out;
    const int N = in_sizes[2];

    static bool attr_set = false;
    if (!attr_set) {
        cudaFuncSetAttribute(knn_fused_kernel,
                             cudaFuncAttributeMaxDynamicSharedMemorySize, SMEM_DYN);
        attr_set = true;
    }
    knn_fused_kernel<<<BLOCKS1, THREADS1, SMEM_DYN>>>(query, mat, pseudo, out, N);
}